// round 6
// baseline (speedup 1.0000x reference)
#include <cuda_runtime.h>
#include <cuda_bf16.h>
#include <cuda_fp16.h>
#include <stdint.h>

#define NN_  100000
#define EE_  1600000
#define DH   128
#define DL   64
#define TOT_CT 6400000u   // N*64 elements of eps

// ---------------- device scratch (no cudaMalloc allowed) ----------------
__device__ float  g_h   [NN_ * DH];   // h after encoder agg (fp32, GEMM2 input)
__device__ float  g_t   [NN_ * DL];   // t = A*z (decoder GEMM input)
__device__ __half g_hf16[NN_ * DH];   // fp16 GEMM outputs (gather operand)
__device__ __half g_zf16[NN_ * DL];   // fp16 copy of z (decoder gather operand)
__device__ float  g_dinv_e[NN_];
__device__ float  g_dinv_1[NN_];
__device__ int    g_cnt [NN_];
__device__ int    g_base[NN_];
__device__ int    g_fill[NN_];
__device__ int2   g_ecsr[EE_];        // packed CSR: {src, __float_as_int(w)}
__device__ int    g_bsum[128];
__device__ float  g_bias2[DH];
__device__ int    g_is64;

// Preconverted weight operand images: W^T as bf16 hi/lo, row-major [128][KP]
__device__ __align__(16) __nv_bfloat16 g_wt_enc_h[128 * 136];
__device__ __align__(16) __nv_bfloat16 g_wt_enc_l[128 * 136];
__device__ __align__(16) __nv_bfloat16 g_wt_mid_h[128 * 136];
__device__ __align__(16) __nv_bfloat16 g_wt_mid_l[128 * 136];
__device__ __align__(16) __nv_bfloat16 g_wt_dec_h[128 * 72];
__device__ __align__(16) __nv_bfloat16 g_wt_dec_l[128 * 72];

// ---------------- edge_index dtype detection ----------------
__global__ void detect_kernel(const unsigned* __restrict__ q) {
    unsigned v = q[threadIdx.x * 2 + 1];
    int any = __syncthreads_or(v != 0u);
    if (threadIdx.x == 0) g_is64 = any ? 0 : 1;
}

__device__ __forceinline__ int2 load_edge(const void* p, int e, int is64) {
    if (is64) {
        const long long* q = (const long long*)p;
        return make_int2((int)q[e], (int)q[EE_ + e]);
    } else {
        const int* q = (const int*)p;
        return make_int2(q[e], q[EE_ + e]);
    }
}

// ---------------- init ----------------
__global__ void init_kernel(const float* __restrict__ b_mu, const float* __restrict__ b_lv) {
    int i = blockIdx.x * blockDim.x + threadIdx.x;
    if (i < NN_) {
        g_cnt[i]  = 0;
        g_fill[i] = 0;
    }
    if (i < DL)       g_bias2[i] = b_mu[i];
    else if (i < DH)  g_bias2[i] = b_lv[i - DL];
}

// ---------------- in-degree count ----------------
__global__ void deg_kernel(const void* __restrict__ ei) {
    int e = blockIdx.x * blockDim.x + threadIdx.x;
    if (e >= EE_) return;
    int d;
    if (g_is64) d = (int)((const long long*)ei)[EE_ + e];
    else        d = ((const int*)ei)[EE_ + e];
    atomicAdd(&g_cnt[d], 1);
}

// ---------------- scans ----------------
__global__ void scan1_kernel() {
    __shared__ int sh[1024];
    int i = blockIdx.x * 1024 + threadIdx.x;
    int v = (i < NN_) ? g_cnt[i] : 0;
    sh[threadIdx.x] = v;
    __syncthreads();
    #pragma unroll
    for (int off = 1; off < 1024; off <<= 1) {
        int t = (threadIdx.x >= off) ? sh[threadIdx.x - off] : 0;
        __syncthreads();
        sh[threadIdx.x] += t;
        __syncthreads();
    }
    if (i < NN_) g_base[i] = sh[threadIdx.x] - v;
    if (threadIdx.x == 1023) g_bsum[blockIdx.x] = sh[1023];
}

__global__ void scan2_kernel(int nblocks) {
    __shared__ int sh[128];
    int v = (threadIdx.x < nblocks) ? g_bsum[threadIdx.x] : 0;
    sh[threadIdx.x] = v;
    __syncthreads();
    #pragma unroll
    for (int off = 1; off < 128; off <<= 1) {
        int t = (threadIdx.x >= off) ? sh[threadIdx.x - off] : 0;
        __syncthreads();
        sh[threadIdx.x] += t;
        __syncthreads();
    }
    g_bsum[threadIdx.x] = sh[threadIdx.x] - v;
}

__global__ void scan3_kernel() {
    int i = blockIdx.x * blockDim.x + threadIdx.x;
    if (i >= NN_) return;
    g_base[i] += g_bsum[i >> 10];
    g_dinv_1[i] = rsqrtf((float)g_cnt[i] + 1.0f);
}

// ---------------- CSR fill (packed) ----------------
__global__ void fill_kernel(const void* __restrict__ ei, const float* __restrict__ ew) {
    int e = blockIdx.x * blockDim.x + threadIdx.x;
    if (e >= EE_) return;
    int is64 = g_is64;
    int2 sd = load_edge(ei, e, is64);
    int slot = g_base[sd.y] + atomicAdd(&g_fill[sd.y], 1);
    g_ecsr[slot] = make_int2(sd.x, __float_as_int(ew[e]));
}

// ---------------- weighted degree from CSR rows ----------------
__global__ void sumw_kernel() {
    int i = blockIdx.x * blockDim.x + threadIdx.x;
    if (i >= NN_) return;
    int b = g_base[i], c = g_cnt[i];
    float s = 0.f;
    for (int p = b; p < b + c; p++) s += __int_as_float(g_ecsr[p].y);
    g_dinv_e[i] = rsqrtf(s + 1.0f);
}

// ---------------- weight convert ----------------
__device__ __forceinline__ void split_bf16(float v, __nv_bfloat16& h, __nv_bfloat16& l) {
    h = __float2bfloat16(v);
    l = __float2bfloat16(v - __bfloat162float(h));
}

__global__ void wconv_kernel(const float* __restrict__ W_enc, const float* __restrict__ W_mu,
                             const float* __restrict__ W_lv,  const float* __restrict__ W_dec) {
    int idx = blockIdx.x * blockDim.x + threadIdx.x;
    if (idx >= 128 * 136) return;
    int n = idx / 136, k = idx % 136;
    __nv_bfloat16 h, l;
    float ve = (k < 128) ? W_enc[k * 128 + n] : 0.f;
    split_bf16(ve, h, l);
    g_wt_enc_h[idx] = h; g_wt_enc_l[idx] = l;
    float vm = 0.f;
    if (k < 128) vm = (n < 64) ? W_mu[k * 64 + n] : W_lv[k * 64 + (n - 64)];
    split_bf16(vm, h, l);
    g_wt_mid_h[idx] = h; g_wt_mid_l[idx] = l;
    if (k < 72) {
        int di = n * 72 + k;
        float vd = (k < 64) ? W_dec[k * 128 + n] : 0.f;
        split_bf16(vd, h, l);
        g_wt_dec_h[di] = h; g_wt_dec_l[di] = l;
    }
}

// ======================= HMMA GEMM (mma.sync m16n8k16 bf16) =======================
__device__ __forceinline__ uint32_t smem_u32(const void* p) {
    uint32_t a;
    asm("{ .reg .u64 t; cvta.to.shared.u64 t, %1; cvt.u32.u64 %0, t; }" : "=r"(a) : "l"(p));
    return a;
}

__device__ __forceinline__ void ldm_x4(uint32_t addr, uint32_t& r0, uint32_t& r1,
                                       uint32_t& r2, uint32_t& r3) {
    asm volatile("ldmatrix.sync.aligned.m8n8.x4.shared.b16 {%0,%1,%2,%3}, [%4];"
                 : "=r"(r0), "=r"(r1), "=r"(r2), "=r"(r3) : "r"(addr));
}

__device__ __forceinline__ void mma16816(float* c, const uint32_t* a, const uint32_t* b) {
    asm volatile(
        "mma.sync.aligned.m16n8k16.row.col.f32.bf16.bf16.f32 "
        "{%0,%1,%2,%3}, {%4,%5,%6,%7}, {%8,%9}, {%0,%1,%2,%3};"
        : "+f"(c[0]), "+f"(c[1]), "+f"(c[2]), "+f"(c[3])
        : "r"(a[0]), "r"(a[1]), "r"(a[2]), "r"(a[3]), "r"(b[0]), "r"(b[1]));
}

template<int KDIM, bool HALF_OUT>
__global__ void __launch_bounds__(256, 1) hmma_gemm_kernel(
        const float* __restrict__ A, int M,
        const __nv_bfloat16* __restrict__ Bh_img, const __nv_bfloat16* __restrict__ Bl_img,
        void* __restrict__ Cout, const float* __restrict__ bias) {
    constexpr int KP = KDIM + 8;
    constexpr int SZ = 128 * KP;
    extern __shared__ __align__(16) __nv_bfloat16 smem[];
    __nv_bfloat16* sAh = smem;
    __nv_bfloat16* sAl = smem + SZ;
    __nv_bfloat16* sBh = smem + 2 * SZ;
    __nv_bfloat16* sBl = smem + 3 * SZ;

    int tid = threadIdx.x, wid = tid >> 5, lane = tid & 31;
    int rowbase = blockIdx.x * 128;

    // stage B
    {
        const uint4* gh = (const uint4*)Bh_img;
        const uint4* gl = (const uint4*)Bl_img;
        uint4* th = (uint4*)sBh;
        uint4* tl = (uint4*)sBl;
        constexpr int NV = SZ * 2 / 16;
        for (int i = tid; i < NV; i += 256) { th[i] = gh[i]; tl[i] = gl[i]; }
    }

    // stage A: fp32 -> bf16 hi/lo
    {
        constexpr int C4 = KDIM / 4;
        for (int i = tid; i < 128 * C4; i += 256) {
            int row = i / C4, col = (i % C4) * 4;
            float4 av = make_float4(0.f, 0.f, 0.f, 0.f);
            if (rowbase + row < M)
                av = *(const float4*)&A[(size_t)(rowbase + row) * KDIM + col];
            __nv_bfloat16 h0, h1, h2, h3, l0, l1, l2, l3;
            split_bf16(av.x, h0, l0); split_bf16(av.y, h1, l1);
            split_bf16(av.z, h2, l2); split_bf16(av.w, h3, l3);
            uint2 hv, lv;
            hv.x = ((uint32_t)__bfloat16_as_ushort(h1) << 16) | __bfloat16_as_ushort(h0);
            hv.y = ((uint32_t)__bfloat16_as_ushort(h3) << 16) | __bfloat16_as_ushort(h2);
            lv.x = ((uint32_t)__bfloat16_as_ushort(l1) << 16) | __bfloat16_as_ushort(l0);
            lv.y = ((uint32_t)__bfloat16_as_ushort(l3) << 16) | __bfloat16_as_ushort(l2);
            int off = row * KP + col;
            *(uint2*)&sAh[off] = hv;
            *(uint2*)&sAl[off] = lv;
        }
        for (int i = tid; i < 128 * 8 / 4; i += 256) {
            int row = i / 2, seg = i % 2;
            int off = row * KP + KDIM + seg * 4;
            *(uint2*)&sAh[off] = make_uint2(0u, 0u);
            *(uint2*)&sAl[off] = make_uint2(0u, 0u);
        }
    }
    __syncthreads();

    int warp_m = (wid >> 2) * 64;
    int warp_n = (wid & 3) * 32;

    float acc[4][4][4];
    #pragma unroll
    for (int a = 0; a < 4; a++)
        #pragma unroll
        for (int b = 0; b < 4; b++)
            #pragma unroll
            for (int r = 0; r < 4; r++) acc[a][b][r] = 0.f;

    uint32_t sAh_base = smem_u32(sAh), sAl_base = smem_u32(sAl);
    uint32_t sBh_base = smem_u32(sBh), sBl_base = smem_u32(sBl);

    int gA = lane >> 3;
    int a_row_off = (lane & 7) + (gA & 1) * 8;
    int a_col_off = (gA >> 1) * 8;
    int gB = lane >> 3;
    int b_row_off = (lane & 7) + (gB >> 1) * 8;
    int b_col_off = (gB & 1) * 8;

    constexpr int NSTEP = KDIM / 16;
    #pragma unroll
    for (int ks = 0; ks < NSTEP; ks++) {
        int k0 = ks * 16;
        uint32_t bh[4][2], bl[4][2];
        #pragma unroll
        for (int ni2 = 0; ni2 < 2; ni2++) {
            uint32_t off = (uint32_t)((warp_n + ni2 * 16 + b_row_off) * KP + k0 + b_col_off) * 2;
            uint32_t r0, r1, r2, r3;
            ldm_x4(sBh_base + off, r0, r1, r2, r3);
            bh[ni2 * 2 + 0][0] = r0; bh[ni2 * 2 + 0][1] = r1;
            bh[ni2 * 2 + 1][0] = r2; bh[ni2 * 2 + 1][1] = r3;
            ldm_x4(sBl_base + off, r0, r1, r2, r3);
            bl[ni2 * 2 + 0][0] = r0; bl[ni2 * 2 + 0][1] = r1;
            bl[ni2 * 2 + 1][0] = r2; bl[ni2 * 2 + 1][1] = r3;
        }
        #pragma unroll
        for (int mi = 0; mi < 4; mi++) {
            uint32_t off = (uint32_t)((warp_m + mi * 16 + a_row_off) * KP + k0 + a_col_off) * 2;
            uint32_t ah[4], al[4];
            ldm_x4(sAh_base + off, ah[0], ah[1], ah[2], ah[3]);
            ldm_x4(sAl_base + off, al[0], al[1], al[2], al[3]);
            #pragma unroll
            for (int ni = 0; ni < 4; ni++) {
                mma16816(acc[mi][ni], ah, bh[ni]);
                mma16816(acc[mi][ni], ah, bl[ni]);
                mma16816(acc[mi][ni], al, bh[ni]);
            }
        }
    }

    int qr = lane >> 2;
    int qc = (lane & 3) * 2;
    #pragma unroll
    for (int mi = 0; mi < 4; mi++) {
        int r0 = rowbase + warp_m + mi * 16 + qr;
        #pragma unroll
        for (int ni = 0; ni < 4; ni++) {
            int col = warp_n + ni * 8 + qc;
            float bx = 0.f, by = 0.f;
            if (bias) { bx = bias[col]; by = bias[col + 1]; }
            if (HALF_OUT) {
                __half* Ch = (__half*)Cout;
                if (r0 < M)
                    *(__half2*)&Ch[(size_t)r0 * 128 + col] =
                        __floats2half2_rn(acc[mi][ni][0] + bx, acc[mi][ni][1] + by);
                if (r0 + 8 < M)
                    *(__half2*)&Ch[(size_t)(r0 + 8) * 128 + col] =
                        __floats2half2_rn(acc[mi][ni][2] + bx, acc[mi][ni][3] + by);
            } else {
                float* Cf = (float*)Cout;
                if (r0 < M)
                    *(float2*)&Cf[(size_t)r0 * 128 + col] =
                        make_float2(acc[mi][ni][0] + bx, acc[mi][ni][1] + by);
                if (r0 + 8 < M)
                    *(float2*)&Cf[(size_t)(r0 + 8) * 128 + col] =
                        make_float2(acc[mi][ni][2] + bx, acc[mi][ni][3] + by);
            }
        }
    }
}

// -------- pipelined fp16 gather body: accumulate into acc (128 cols, lane*4) --------
__device__ __forceinline__ void agg_loop128(const __half* __restrict__ hin, int w, int lane,
                                            float dd, bool use_w, float4& acc) {
    int beg = g_base[w];
    int end = beg + g_cnt[w];
    int2 e0, e1;
    if (beg < end)     e0 = g_ecsr[beg];
    if (beg + 1 < end) e1 = g_ecsr[beg + 1];
    for (int p = beg; p < end; p += 2) {
        int2 c0 = e0, c1 = e1;
        bool has1 = (p + 1 < end);
        if (p + 2 < end) e0 = g_ecsr[p + 2];
        if (p + 3 < end) e1 = g_ecsr[p + 3];
        float n0 = g_dinv_1[c0.x];
        float n1 = 0.f;
        uint2 r0 = *(const uint2*)&hin[(size_t)c0.x * DH + lane * 4];
        uint2 r1 = r0;
        if (has1) {
            n1 = g_dinv_1[c1.x];
            r1 = *(const uint2*)&hin[(size_t)c1.x * DH + lane * 4];
        }
        if (use_w) {
            // weighted layer uses dinv_e, not dinv_1
            n0 = g_dinv_e[c0.x] * __int_as_float(c0.y);
            n1 = has1 ? g_dinv_e[c1.x] * __int_as_float(c1.y) : 0.f;
        }
        n0 *= dd; n1 *= dd;
        float2 a01 = __half22float2(*(__half2*)&r0.x);
        float2 a23 = __half22float2(*(__half2*)&r0.y);
        float2 b01 = __half22float2(*(__half2*)&r1.x);
        float2 b23 = __half22float2(*(__half2*)&r1.y);
        acc.x = fmaf(n0, a01.x, fmaf(n1, b01.x, acc.x));
        acc.y = fmaf(n0, a01.y, fmaf(n1, b01.y, acc.y));
        acc.z = fmaf(n0, a23.x, fmaf(n1, b23.x, acc.z));
        acc.w = fmaf(n0, a23.y, fmaf(n1, b23.y, acc.w));
    }
}

// ---------------- encoder aggregation (weighted, fp16 in -> fp32 out) ----------------
__global__ void aggh_kernel(const __half* __restrict__ hin, float* __restrict__ hout,
                            const float* __restrict__ bias) {
    int w = (blockIdx.x * blockDim.x + threadIdx.x) >> 5;
    int lane = threadIdx.x & 31;
    if (w >= NN_) return;
    float dd = g_dinv_e[w];
    float4 b4 = *(const float4*)&bias[lane * 4];
    uint2 sraw = *(const uint2*)&hin[(size_t)w * DH + lane * 4];
    float2 s01 = __half22float2(*(__half2*)&sraw.x);
    float2 s23 = __half22float2(*(__half2*)&sraw.y);
    float sn = dd * dd;
    float4 acc;
    acc.x = fmaf(s01.x, sn, b4.x);
    acc.y = fmaf(s01.y, sn, b4.y);
    acc.z = fmaf(s23.x, sn, b4.z);
    acc.w = fmaf(s23.y, sn, b4.w);
    agg_loop128(hin, w, lane, dd, true, acc);
    *(float4*)&hout[(size_t)w * DH + lane * 4] = acc;
}

// ---------------- threefry2x32 (JAX key(42)), PARTITIONABLE mode ----------------
__device__ __forceinline__ void tf_round(uint32_t& x0, uint32_t& x1, int r) {
    x0 += x1;
    x1 = (x1 << r) | (x1 >> (32 - r));
    x1 ^= x0;
}

__device__ __forceinline__ uint32_t threefry_bits_partitionable(uint32_t i) {
    const uint32_t ks0 = 0u, ks1 = 42u, ks2 = 0x1BD11BDAu ^ 42u;
    uint32_t x0 = 0u + ks0, x1 = i + ks1;
    tf_round(x0, x1, 13); tf_round(x0, x1, 15); tf_round(x0, x1, 26); tf_round(x0, x1, 6);
    x0 += ks1; x1 += ks2 + 1u;
    tf_round(x0, x1, 17); tf_round(x0, x1, 29); tf_round(x0, x1, 16); tf_round(x0, x1, 24);
    x0 += ks2; x1 += ks0 + 2u;
    tf_round(x0, x1, 13); tf_round(x0, x1, 15); tf_round(x0, x1, 26); tf_round(x0, x1, 6);
    x0 += ks0; x1 += ks1 + 3u;
    tf_round(x0, x1, 17); tf_round(x0, x1, 29); tf_round(x0, x1, 16); tf_round(x0, x1, 24);
    x0 += ks1; x1 += ks2 + 4u;
    tf_round(x0, x1, 13); tf_round(x0, x1, 15); tf_round(x0, x1, 26); tf_round(x0, x1, 6);
    x0 += ks2; x1 += ks0 + 5u;
    return x0 ^ x1;
}

__device__ __forceinline__ float erfinv_xla(float x) {
    float w = -log1pf(-x * x);
    float p;
    if (w < 5.0f) {
        w -= 2.5f;
        p = 2.81022636e-08f;
        p = fmaf(p, w, 3.43273939e-07f);
        p = fmaf(p, w, -3.5233877e-06f);
        p = fmaf(p, w, -4.39150654e-06f);
        p = fmaf(p, w, 0.00021858087f);
        p = fmaf(p, w, -0.00125372503f);
        p = fmaf(p, w, -0.00417768164f);
        p = fmaf(p, w, 0.246640727f);
        p = fmaf(p, w, 1.50140941f);
    } else {
        w = sqrtf(w) - 3.0f;
        p = -0.000200214257f;
        p = fmaf(p, w, 0.000100950558f);
        p = fmaf(p, w, 0.00134934322f);
        p = fmaf(p, w, -0.00367342844f);
        p = fmaf(p, w, 0.00573950773f);
        p = fmaf(p, w, -0.0076224613f);
        p = fmaf(p, w, 0.00943887047f);
        p = fmaf(p, w, 1.00167406f);
        p = fmaf(p, w, 2.83297682f);
    }
    return p * x;
}

__device__ __forceinline__ float bits_to_normal(uint32_t b) {
    float f = __uint_as_float((b >> 9) | 0x3f800000u) - 1.0f;
    const float lo = -0.99999994f;
    float u = __fmul_rn(f, 2.0f);
    u = __fadd_rn(u, lo);
    u = fmaxf(u, lo);
    return 1.4142135623730951f * erfinv_xla(u);
}

// ---------------- fused mid aggregation + reparameterization ----------------
// Aggregates [mu|lv] (128 cols) per node and computes z inline.
// Lanes 0-15 hold mu cols (4*lane..), lanes 16-31 hold lv cols.
__global__ void aggz_kernel(const __half* __restrict__ hin,
                            float* __restrict__ o_z, float* __restrict__ o_mu,
                            float* __restrict__ o_lv) {
    int w = (blockIdx.x * blockDim.x + threadIdx.x) >> 5;
    int lane = threadIdx.x & 31;
    if (w >= NN_) return;
    float dd = g_dinv_1[w];
    float4 b4 = *(const float4*)&g_bias2[lane * 4];
    uint2 sraw = *(const uint2*)&hin[(size_t)w * DH + lane * 4];
    float2 s01 = __half22float2(*(__half2*)&sraw.x);
    float2 s23 = __half22float2(*(__half2*)&sraw.y);
    float sn = dd * dd;
    float4 acc;
    acc.x = fmaf(s01.x, sn, b4.x);
    acc.y = fmaf(s01.y, sn, b4.y);
    acc.z = fmaf(s23.x, sn, b4.z);
    acc.w = fmaf(s23.y, sn, b4.w);
    agg_loop128(hin, w, lane, dd, false, acc);

    // lane l<16: acc = mu[4l..4l+3]; lane l>=16: acc = lv[4(l-16)..]
    float4 lvv;
    lvv.x = __shfl_sync(0xffffffffu, acc.x, lane + 16);
    lvv.y = __shfl_sync(0xffffffffu, acc.y, lane + 16);
    lvv.z = __shfl_sync(0xffffffffu, acc.z, lane + 16);
    lvv.w = __shfl_sync(0xffffffffu, acc.w, lane + 16);

    if (lane < 16) {
        unsigned base = (unsigned)w * 64u + (unsigned)lane * 4u;
        *(float4*)&o_mu[base] = acc;
        float z0 = __fadd_rn(acc.x, __fmul_rn(bits_to_normal(threefry_bits_partitionable(base + 0)), expf(0.5f * lvv.x)));
        float z1 = __fadd_rn(acc.y, __fmul_rn(bits_to_normal(threefry_bits_partitionable(base + 1)), expf(0.5f * lvv.y)));
        float z2 = __fadd_rn(acc.z, __fmul_rn(bits_to_normal(threefry_bits_partitionable(base + 2)), expf(0.5f * lvv.z)));
        float z3 = __fadd_rn(acc.w, __fmul_rn(bits_to_normal(threefry_bits_partitionable(base + 3)), expf(0.5f * lvv.w)));
        *(float4*)&o_z[base] = make_float4(z0, z1, z2, z3);
        uint2 zf;
        *(__half2*)&zf.x = __floats2half2_rn(z0, z1);
        *(__half2*)&zf.y = __floats2half2_rn(z2, z3);
        *(uint2*)&g_zf16[base] = zf;
    } else {
        unsigned base = (unsigned)w * 64u + (unsigned)(lane - 16) * 4u;
        *(float4*)&o_lv[base] = acc;
    }
}

// ---------------- decoder aggregation over fp16 z (64-dim, pipelined) ----------------
__global__ void agg64h_kernel(const __half* __restrict__ zin, float* __restrict__ t) {
    int w = (blockIdx.x * blockDim.x + threadIdx.x) >> 5;
    int lane = threadIdx.x & 31;
    if (w >= NN_) return;
    float dd = g_dinv_1[w];
    float sn = dd * dd;
    uint32_t sraw = *(const uint32_t*)&zin[(size_t)w * DL + lane * 2];
    float2 sv = __half22float2(*(__half2*)&sraw);
    float2 acc = make_float2(sv.x * sn, sv.y * sn);
    int beg = g_base[w];
    int end = beg + g_cnt[w];
    int2 e0, e1;
    if (beg < end)     e0 = g_ecsr[beg];
    if (beg + 1 < end) e1 = g_ecsr[beg + 1];
    for (int p = beg; p < end; p += 2) {
        int2 c0 = e0, c1 = e1;
        bool has1 = (p + 1 < end);
        if (p + 2 < end) e0 = g_ecsr[p + 2];
        if (p + 3 < end) e1 = g_ecsr[p + 3];
        float n0 = g_dinv_1[c0.x] * dd;
        float n1 = 0.f;
        uint32_t r0 = *(const uint32_t*)&zin[(size_t)c0.x * DL + lane * 2];
        uint32_t r1 = r0;
        if (has1) {
            n1 = g_dinv_1[c1.x] * dd;
            r1 = *(const uint32_t*)&zin[(size_t)c1.x * DL + lane * 2];
        }
        float2 v0 = __half22float2(*(__half2*)&r0);
        float2 v1 = __half22float2(*(__half2*)&r1);
        acc.x = fmaf(n0, v0.x, fmaf(n1, v1.x, acc.x));
        acc.y = fmaf(n0, v0.y, fmaf(n1, v1.y, acc.y));
    }
    *(float2*)&t[(size_t)w * DL + lane * 2] = acc;
}

// ---------------- launch ----------------
extern "C" void kernel_launch(void* const* d_in, const int* in_sizes, int n_in,
                              void* d_out, int out_size) {
    const float* x     = (const float*)d_in[0];
    const float* ew    = (const float*)d_in[1];
    const float* W_enc = (const float*)d_in[2];
    const float* b_enc = (const float*)d_in[3];
    const float* W_mu  = (const float*)d_in[4];
    const float* b_mu  = (const float*)d_in[5];
    const float* W_lv  = (const float*)d_in[6];
    const float* b_lv  = (const float*)d_in[7];
    const float* W_dec = (const float*)d_in[8];
    const float* b_dec = (const float*)d_in[9];
    const void*  eidx  = d_in[10];

    float* out   = (float*)d_out;
    float* o_z   = out;                       // [N,64]
    float* o_rec = out + (size_t)NN_ * DL;    // [N,128]
    float* o_mu  = o_rec + (size_t)NN_ * DH;  // [N,64]
    float* o_lv  = o_mu + (size_t)NN_ * DL;   // [N,64]

    float *p_h, *p_t;
    __half *p_hf16, *p_zf16;
    __nv_bfloat16 *p_we_h, *p_we_l, *p_wm_h, *p_wm_l, *p_wd_h, *p_wd_l;
    cudaGetSymbolAddress((void**)&p_h, g_h);
    cudaGetSymbolAddress((void**)&p_t, g_t);
    cudaGetSymbolAddress((void**)&p_hf16, g_hf16);
    cudaGetSymbolAddress((void**)&p_zf16, g_zf16);
    cudaGetSymbolAddress((void**)&p_we_h, g_wt_enc_h);
    cudaGetSymbolAddress((void**)&p_we_l, g_wt_enc_l);
    cudaGetSymbolAddress((void**)&p_wm_h, g_wt_mid_h);
    cudaGetSymbolAddress((void**)&p_wm_l, g_wt_mid_l);
    cudaGetSymbolAddress((void**)&p_wd_h, g_wt_dec_h);
    cudaGetSymbolAddress((void**)&p_wd_l, g_wt_dec_l);

    const int NB_SCAN = (NN_ + 1023) / 1024;           // 98
    const int GEMM_GRID = (NN_ + 127) / 128;           // 782
    const int SMEM128 = 4 * 128 * 136 * 2;             // 139264
    const int SMEM64  = 4 * 128 * 72 * 2;              // 73728

    cudaFuncSetAttribute(hmma_gemm_kernel<128, true>,  cudaFuncAttributeMaxDynamicSharedMemorySize, SMEM128);
    cudaFuncSetAttribute(hmma_gemm_kernel<64, false>,  cudaFuncAttributeMaxDynamicSharedMemorySize, SMEM64);

    // NOTE: launch order puts GEMM1 at index 3 so the fixed ncu capture slot
    // profiles the HMMA GEMM instead of a tiny preprocessing kernel.
    detect_kernel<<<1, 128>>>((const unsigned*)eidx);                                   // 0
    wconv_kernel<<<(128 * 136 + 255) / 256, 256>>>(W_enc, W_mu, W_lv, W_dec);           // 1
    init_kernel<<<(NN_ + 255) / 256, 256>>>(b_mu, b_lv);                                // 2
    hmma_gemm_kernel<128, true><<<GEMM_GRID, 256, SMEM128>>>(x, NN_, p_we_h, p_we_l, p_hf16, nullptr); // 3 (PROFILED)
    deg_kernel<<<(EE_ + 255) / 256, 256>>>(eidx);                                       // 4
    scan1_kernel<<<NB_SCAN, 1024>>>();                                                  // 5
    scan2_kernel<<<1, 128>>>(NB_SCAN);                                                  // 6
    scan3_kernel<<<(NN_ + 255) / 256, 256>>>();                                         // 7
    fill_kernel<<<(EE_ + 255) / 256, 256>>>(eidx, ew);                                  // 8
    sumw_kernel<<<(NN_ + 255) / 256, 256>>>();                                          // 9

    // encoder agg: h = agg_w(hf16) + b_enc   (fp32 out, GEMM2 input)
    aggh_kernel<<<(NN_ * 32 + 255) / 256, 256>>>(p_hf16, p_h, b_enc);                   // 10
    // mid GEMM: hf16 = h @ [W_mu|W_lv]
    hmma_gemm_kernel<128, true><<<GEMM_GRID, 256, SMEM128>>>(p_h, NN_, p_wm_h, p_wm_l, p_hf16, nullptr); // 11
    // fused mid agg + reparam: writes o_mu, o_lv, o_z, zf16
    aggz_kernel<<<(NN_ * 32 + 255) / 256, 256>>>(p_hf16, o_z, o_mu, o_lv);              // 12
    // decoder agg: t = agg(z_fp16)
    agg64h_kernel<<<(NN_ * 32 + 255) / 256, 256>>>(p_zf16, p_t);                        // 13
    // decoder GEMM: recon = t @ W_dec + b_dec
    hmma_gemm_kernel<64, false><<<GEMM_GRID, 256, SMEM64>>>(p_t, NN_, p_wd_h, p_wd_l, o_rec, b_dec); // 14
}

// round 7
// speedup vs baseline: 1.3408x; 1.3408x over previous
#include <cuda_runtime.h>
#include <cuda_bf16.h>
#include <cuda_fp16.h>
#include <stdint.h>

#define NN_  100000
#define EE_  1600000
#define DH   128
#define DL   64

// ---------------- device scratch (no cudaMalloc allowed) ----------------
__device__ float  g_h   [NN_ * DH];   // h after encoder agg (fp32, GEMM2 input)
__device__ float  g_t   [NN_ * DL];   // t = A*z (decoder GEMM input)
__device__ __half g_hf16[NN_ * DH];   // fp16 GEMM outputs (gather operand)
__device__ __half g_zf16[NN_ * DL];   // fp16 copy of z (decoder gather operand)
__device__ float  g_dinv_e[NN_];
__device__ float  g_dinv_1[NN_];
__device__ int    g_cnt [NN_];
__device__ int    g_base[NN_];
__device__ int    g_fill[NN_];
__device__ int2   g_ecsr[EE_];        // packed CSR: {src, __float_as_int(w)}
__device__ int    g_bsum[128];
__device__ float  g_bias2[DH];
__device__ int    g_is64;

// B operands precomputed in mma fragment layout:
//   uint4 {bh0, bh1, bl0, bl1} indexed by ((kstep*16 + nfrag)*32 + lane)
//   nfrag = n8 index (16 total for N=128), kstep = k16 index.
__device__ __align__(16) uint4 g_bfrag_enc[8 * 16 * 32];   // 64KB
__device__ __align__(16) uint4 g_bfrag_mid[8 * 16 * 32];   // 64KB
__device__ __align__(16) uint4 g_bfrag_dec[4 * 16 * 32];   // 32KB

// ---------------- edge_index dtype detection ----------------
__global__ void detect_kernel(const unsigned* __restrict__ q) {
    unsigned v = q[threadIdx.x * 2 + 1];
    int any = __syncthreads_or(v != 0u);
    if (threadIdx.x == 0) g_is64 = any ? 0 : 1;
}

__device__ __forceinline__ int2 load_edge(const void* p, int e, int is64) {
    if (is64) {
        const long long* q = (const long long*)p;
        return make_int2((int)q[e], (int)q[EE_ + e]);
    } else {
        const int* q = (const int*)p;
        return make_int2(q[e], q[EE_ + e]);
    }
}

// ---------------- init ----------------
__global__ void init_kernel(const float* __restrict__ b_mu, const float* __restrict__ b_lv) {
    int i = blockIdx.x * blockDim.x + threadIdx.x;
    if (i < NN_) {
        g_cnt[i]  = 0;
        g_fill[i] = 0;
    }
    if (i < DL)       g_bias2[i] = b_mu[i];
    else if (i < DH)  g_bias2[i] = b_lv[i - DL];
}

// ---------------- in-degree count ----------------
__global__ void deg_kernel(const void* __restrict__ ei) {
    int e = blockIdx.x * blockDim.x + threadIdx.x;
    if (e >= EE_) return;
    int d;
    if (g_is64) d = (int)((const long long*)ei)[EE_ + e];
    else        d = ((const int*)ei)[EE_ + e];
    atomicAdd(&g_cnt[d], 1);
}

// ---------------- scans ----------------
__global__ void scan1_kernel() {
    __shared__ int sh[1024];
    int i = blockIdx.x * 1024 + threadIdx.x;
    int v = (i < NN_) ? g_cnt[i] : 0;
    sh[threadIdx.x] = v;
    __syncthreads();
    #pragma unroll
    for (int off = 1; off < 1024; off <<= 1) {
        int t = (threadIdx.x >= off) ? sh[threadIdx.x - off] : 0;
        __syncthreads();
        sh[threadIdx.x] += t;
        __syncthreads();
    }
    if (i < NN_) g_base[i] = sh[threadIdx.x] - v;
    if (threadIdx.x == 1023) g_bsum[blockIdx.x] = sh[1023];
}

__global__ void scan2_kernel(int nblocks) {
    __shared__ int sh[128];
    int v = (threadIdx.x < nblocks) ? g_bsum[threadIdx.x] : 0;
    sh[threadIdx.x] = v;
    __syncthreads();
    #pragma unroll
    for (int off = 1; off < 128; off <<= 1) {
        int t = (threadIdx.x >= off) ? sh[threadIdx.x - off] : 0;
        __syncthreads();
        sh[threadIdx.x] += t;
        __syncthreads();
    }
    g_bsum[threadIdx.x] = sh[threadIdx.x] - v;
}

__global__ void scan3_kernel() {
    int i = blockIdx.x * blockDim.x + threadIdx.x;
    if (i >= NN_) return;
    g_base[i] += g_bsum[i >> 10];
    g_dinv_1[i] = rsqrtf((float)g_cnt[i] + 1.0f);
}

// ---------------- CSR fill (packed) ----------------
__global__ void fill_kernel(const void* __restrict__ ei, const float* __restrict__ ew) {
    int e = blockIdx.x * blockDim.x + threadIdx.x;
    if (e >= EE_) return;
    int is64 = g_is64;
    int2 sd = load_edge(ei, e, is64);
    int slot = g_base[sd.y] + atomicAdd(&g_fill[sd.y], 1);
    g_ecsr[slot] = make_int2(sd.x, __float_as_int(ew[e]));
}

// ---------------- weighted degree from CSR rows ----------------
__global__ void sumw_kernel() {
    int i = blockIdx.x * blockDim.x + threadIdx.x;
    if (i >= NN_) return;
    int b = g_base[i], c = g_cnt[i];
    float s = 0.f;
    for (int p = b; p < b + c; p++) s += __int_as_float(g_ecsr[p].y);
    g_dinv_e[i] = rsqrtf(s + 1.0f);
}

// ---------------- B fragment precompute ----------------
// mma.m16n8k16 B-operand lane map: n = nfrag*8 + (lane>>2); b0 = k16_base + (lane&3)*2 + {0,1},
// b1 = same + 8. Low 16 bits = lower k.
__device__ __forceinline__ uint32_t pack_bf16(float a, float b) {
    return ((uint32_t)__bfloat16_as_ushort(__float2bfloat16(b)) << 16) |
           __bfloat16_as_ushort(__float2bfloat16(a));
}
__device__ __forceinline__ uint32_t pack_bf16_lo(float a, float b) {
    float ah = __bfloat162float(__float2bfloat16(a));
    float bh = __bfloat162float(__float2bfloat16(b));
    return pack_bf16(a - ah, b - bh);
}

__global__ void bfrag_kernel(const float* __restrict__ W_enc, const float* __restrict__ W_mu,
                             const float* __restrict__ W_lv,  const float* __restrict__ W_dec) {
    int t = blockIdx.x * blockDim.x + threadIdx.x;
    if (t >= 8 * 16 * 32) return;
    int lane = t & 31, nf = (t >> 5) & 15, ks = t >> 9;
    int n = nf * 8 + (lane >> 2);
    int k = ks * 16 + (lane & 3) * 2;

    // enc: Wt[n][k] = W_enc[k][n], K=128
    {
        float v0 = W_enc[k * 128 + n],       v1 = W_enc[(k + 1) * 128 + n];
        float v8 = W_enc[(k + 8) * 128 + n], v9 = W_enc[(k + 9) * 128 + n];
        g_bfrag_enc[t] = make_uint4(pack_bf16(v0, v1), pack_bf16(v8, v9),
                                    pack_bf16_lo(v0, v1), pack_bf16_lo(v8, v9));
    }
    // mid: [W_mu | W_lv], K=128
    {
        const float* Wn = (n < 64) ? W_mu : W_lv;
        int nn = (n < 64) ? n : n - 64;
        float v0 = Wn[k * 64 + nn],       v1 = Wn[(k + 1) * 64 + nn];
        float v8 = Wn[(k + 8) * 64 + nn], v9 = Wn[(k + 9) * 64 + nn];
        g_bfrag_mid[t] = make_uint4(pack_bf16(v0, v1), pack_bf16(v8, v9),
                                    pack_bf16_lo(v0, v1), pack_bf16_lo(v8, v9));
    }
    // dec: K=64 -> 4 ksteps
    if (ks < 4) {
        float v0 = W_dec[k * 128 + n],       v1 = W_dec[(k + 1) * 128 + n];
        float v8 = W_dec[(k + 8) * 128 + n], v9 = W_dec[(k + 9) * 128 + n];
        g_bfrag_dec[t] = make_uint4(pack_bf16(v0, v1), pack_bf16(v8, v9),
                                    pack_bf16_lo(v0, v1), pack_bf16_lo(v8, v9));
    }
}

// ======================= HMMA GEMM (mma.sync m16n8k16 bf16) =======================
__device__ __forceinline__ uint32_t smem_u32(const void* p) {
    uint32_t a;
    asm("{ .reg .u64 t; cvta.to.shared.u64 t, %1; cvt.u32.u64 %0, t; }" : "=r"(a) : "l"(p));
    return a;
}

__device__ __forceinline__ void ldm_x4(uint32_t addr, uint32_t& r0, uint32_t& r1,
                                       uint32_t& r2, uint32_t& r3) {
    asm volatile("ldmatrix.sync.aligned.m8n8.x4.shared.b16 {%0,%1,%2,%3}, [%4];"
                 : "=r"(r0), "=r"(r1), "=r"(r2), "=r"(r3) : "r"(addr));
}

__device__ __forceinline__ void mma16816(float* c, const uint32_t* a, const uint32_t* b) {
    asm volatile(
        "mma.sync.aligned.m16n8k16.row.col.f32.bf16.bf16.f32 "
        "{%0,%1,%2,%3}, {%4,%5,%6,%7}, {%8,%9}, {%0,%1,%2,%3};"
        : "+f"(c[0]), "+f"(c[1]), "+f"(c[2]), "+f"(c[3])
        : "r"(a[0]), "r"(a[1]), "r"(a[2]), "r"(a[3]), "r"(b[0]), "r"(b[1]));
}

__device__ __forceinline__ void split_bf16(float v, __nv_bfloat16& h, __nv_bfloat16& l) {
    h = __float2bfloat16(v);
    l = __float2bfloat16(v - __bfloat162float(h));
}

// C[M,128] = A[M,KDIM] @ W^T with bf16x3 split. CTA tile 64x128, 8 warps (2x4), warp 32x32.
// B comes from precomputed fragment array (L1/L2-resident), A staged hi/lo in SMEM.
template<int KDIM, bool HALF_OUT>
__global__ void __launch_bounds__(256) hmma_gemm_kernel(
        const float* __restrict__ A, int M,
        const uint4* __restrict__ bfrag,
        void* __restrict__ Cout, const float* __restrict__ bias) {
    constexpr int KP = KDIM + 8;
    __shared__ __align__(16) __nv_bfloat16 sAh[64 * KP];
    __shared__ __align__(16) __nv_bfloat16 sAl[64 * KP];

    int tid = threadIdx.x, wid = tid >> 5, lane = tid & 31;
    int rowbase = blockIdx.x * 64;

    // stage A: fp32 -> bf16 hi/lo
    {
        constexpr int C4 = KDIM / 4;
        for (int i = tid; i < 64 * C4; i += 256) {
            int row = i / C4, col = (i % C4) * 4;
            float4 av = make_float4(0.f, 0.f, 0.f, 0.f);
            if (rowbase + row < M)
                av = *(const float4*)&A[(size_t)(rowbase + row) * KDIM + col];
            __nv_bfloat16 h0, h1, h2, h3, l0, l1, l2, l3;
            split_bf16(av.x, h0, l0); split_bf16(av.y, h1, l1);
            split_bf16(av.z, h2, l2); split_bf16(av.w, h3, l3);
            uint2 hv, lv;
            hv.x = ((uint32_t)__bfloat16_as_ushort(h1) << 16) | __bfloat16_as_ushort(h0);
            hv.y = ((uint32_t)__bfloat16_as_ushort(h3) << 16) | __bfloat16_as_ushort(h2);
            lv.x = ((uint32_t)__bfloat16_as_ushort(l1) << 16) | __bfloat16_as_ushort(l0);
            lv.y = ((uint32_t)__bfloat16_as_ushort(l3) << 16) | __bfloat16_as_ushort(l2);
            int off = row * KP + col;
            *(uint2*)&sAh[off] = hv;
            *(uint2*)&sAl[off] = lv;
        }
        for (int i = tid; i < 64 * 8 / 4; i += 256) {
            int row = i / 2, seg = i % 2;
            int off = row * KP + KDIM + seg * 4;
            *(uint2*)&sAh[off] = make_uint2(0u, 0u);
            *(uint2*)&sAl[off] = make_uint2(0u, 0u);
        }
    }
    __syncthreads();

    int warp_m = (wid >> 2) * 32;          // 0 or 32
    int warp_n = (wid & 3) * 32;           // 0,32,64,96
    int nf_base = (wid & 3) * 4;           // first n8 frag index

    float acc[2][4][4];
    #pragma unroll
    for (int a = 0; a < 2; a++)
        #pragma unroll
        for (int b = 0; b < 4; b++)
            #pragma unroll
            for (int r = 0; r < 4; r++) acc[a][b][r] = 0.f;

    uint32_t sAh_base = smem_u32(sAh), sAl_base = smem_u32(sAl);
    int gA = lane >> 3;
    int a_row_off = (lane & 7) + (gA & 1) * 8;
    int a_col_off = (gA >> 1) * 8;

    constexpr int NSTEP = KDIM / 16;
    #pragma unroll
    for (int ks = 0; ks < NSTEP; ks++) {
        int k0 = ks * 16;
        uint32_t bh[4][2], bl[4][2];
        #pragma unroll
        for (int ni = 0; ni < 4; ni++) {
            uint4 f = bfrag[(ks * 16 + nf_base + ni) * 32 + lane];
            bh[ni][0] = f.x; bh[ni][1] = f.y;
            bl[ni][0] = f.z; bl[ni][1] = f.w;
        }
        #pragma unroll
        for (int mi = 0; mi < 2; mi++) {
            uint32_t off = (uint32_t)((warp_m + mi * 16 + a_row_off) * KP + k0 + a_col_off) * 2;
            uint32_t ah[4], al[4];
            ldm_x4(sAh_base + off, ah[0], ah[1], ah[2], ah[3]);
            ldm_x4(sAl_base + off, al[0], al[1], al[2], al[3]);
            #pragma unroll
            for (int ni = 0; ni < 4; ni++) {
                mma16816(acc[mi][ni], ah, bh[ni]);
                mma16816(acc[mi][ni], ah, bl[ni]);
                mma16816(acc[mi][ni], al, bh[ni]);
            }
        }
    }

    // epilogue
    int qr = lane >> 2;
    int qc = (lane & 3) * 2;
    #pragma unroll
    for (int mi = 0; mi < 2; mi++) {
        int r0 = rowbase + warp_m + mi * 16 + qr;
        #pragma unroll
        for (int ni = 0; ni < 4; ni++) {
            int col = warp_n + ni * 8 + qc;
            float bx = 0.f, by = 0.f;
            if (bias) { bx = bias[col]; by = bias[col + 1]; }
            if (HALF_OUT) {
                __half* Ch = (__half*)Cout;
                if (r0 < M)
                    *(__half2*)&Ch[(size_t)r0 * 128 + col] =
                        __floats2half2_rn(acc[mi][ni][0] + bx, acc[mi][ni][1] + by);
                if (r0 + 8 < M)
                    *(__half2*)&Ch[(size_t)(r0 + 8) * 128 + col] =
                        __floats2half2_rn(acc[mi][ni][2] + bx, acc[mi][ni][3] + by);
            } else {
                float* Cf = (float*)Cout;
                if (r0 < M)
                    *(float2*)&Cf[(size_t)r0 * 128 + col] =
                        make_float2(acc[mi][ni][0] + bx, acc[mi][ni][1] + by);
                if (r0 + 8 < M)
                    *(float2*)&Cf[(size_t)(r0 + 8) * 128 + col] =
                        make_float2(acc[mi][ni][2] + bx, acc[mi][ni][3] + by);
            }
        }
    }
}

// ---------------- encoder aggregation (weighted, fp16 in -> fp32 out, simple loop) ----------------
__global__ void aggh_kernel(const __half* __restrict__ hin, float* __restrict__ hout,
                            const float* __restrict__ bias) {
    int w = (blockIdx.x * blockDim.x + threadIdx.x) >> 5;
    int lane = threadIdx.x & 31;
    if (w >= NN_) return;
    float dd = g_dinv_e[w];
    float4 b4 = *(const float4*)&bias[lane * 4];
    uint2 sraw = *(const uint2*)&hin[(size_t)w * DH + lane * 4];
    float2 s01 = __half22float2(*(__half2*)&sraw.x);
    float2 s23 = __half22float2(*(__half2*)&sraw.y);
    float sn = dd * dd;
    float4 acc;
    acc.x = fmaf(s01.x, sn, b4.x);
    acc.y = fmaf(s01.y, sn, b4.y);
    acc.z = fmaf(s23.x, sn, b4.z);
    acc.w = fmaf(s23.y, sn, b4.w);
    int beg = g_base[w];
    int end = beg + g_cnt[w];
    for (int p = beg; p < end; p++) {
        int2 c = g_ecsr[p];
        float nrm = g_dinv_e[c.x] * __int_as_float(c.y) * dd;
        uint2 vr = *(const uint2*)&hin[(size_t)c.x * DH + lane * 4];
        float2 v01 = __half22float2(*(__half2*)&vr.x);
        float2 v23 = __half22float2(*(__half2*)&vr.y);
        acc.x = fmaf(nrm, v01.x, acc.x);
        acc.y = fmaf(nrm, v01.y, acc.y);
        acc.z = fmaf(nrm, v23.x, acc.z);
        acc.w = fmaf(nrm, v23.y, acc.w);
    }
    *(float4*)&hout[(size_t)w * DH + lane * 4] = acc;
}

// ---------------- threefry2x32 (JAX key(42)), PARTITIONABLE mode ----------------
__device__ __forceinline__ void tf_round(uint32_t& x0, uint32_t& x1, int r) {
    x0 += x1;
    x1 = (x1 << r) | (x1 >> (32 - r));
    x1 ^= x0;
}

__device__ __forceinline__ uint32_t threefry_bits_partitionable(uint32_t i) {
    const uint32_t ks0 = 0u, ks1 = 42u, ks2 = 0x1BD11BDAu ^ 42u;
    uint32_t x0 = 0u + ks0, x1 = i + ks1;
    tf_round(x0, x1, 13); tf_round(x0, x1, 15); tf_round(x0, x1, 26); tf_round(x0, x1, 6);
    x0 += ks1; x1 += ks2 + 1u;
    tf_round(x0, x1, 17); tf_round(x0, x1, 29); tf_round(x0, x1, 16); tf_round(x0, x1, 24);
    x0 += ks2; x1 += ks0 + 2u;
    tf_round(x0, x1, 13); tf_round(x0, x1, 15); tf_round(x0, x1, 26); tf_round(x0, x1, 6);
    x0 += ks0; x1 += ks1 + 3u;
    tf_round(x0, x1, 17); tf_round(x0, x1, 29); tf_round(x0, x1, 16); tf_round(x0, x1, 24);
    x0 += ks1; x1 += ks2 + 4u;
    tf_round(x0, x1, 13); tf_round(x0, x1, 15); tf_round(x0, x1, 26); tf_round(x0, x1, 6);
    x0 += ks2; x1 += ks0 + 5u;
    return x0 ^ x1;
}

__device__ __forceinline__ float erfinv_xla(float x) {
    float w = -log1pf(-x * x);
    float p;
    if (w < 5.0f) {
        w -= 2.5f;
        p = 2.81022636e-08f;
        p = fmaf(p, w, 3.43273939e-07f);
        p = fmaf(p, w, -3.5233877e-06f);
        p = fmaf(p, w, -4.39150654e-06f);
        p = fmaf(p, w, 0.00021858087f);
        p = fmaf(p, w, -0.00125372503f);
        p = fmaf(p, w, -0.00417768164f);
        p = fmaf(p, w, 0.246640727f);
        p = fmaf(p, w, 1.50140941f);
    } else {
        w = sqrtf(w) - 3.0f;
        p = -0.000200214257f;
        p = fmaf(p, w, 0.000100950558f);
        p = fmaf(p, w, 0.00134934322f);
        p = fmaf(p, w, -0.00367342844f);
        p = fmaf(p, w, 0.00573950773f);
        p = fmaf(p, w, -0.0076224613f);
        p = fmaf(p, w, 0.00943887047f);
        p = fmaf(p, w, 1.00167406f);
        p = fmaf(p, w, 2.83297682f);
    }
    return p * x;
}

__device__ __forceinline__ float bits_to_normal(uint32_t b) {
    float f = __uint_as_float((b >> 9) | 0x3f800000u) - 1.0f;
    const float lo = -0.99999994f;
    float u = __fmul_rn(f, 2.0f);
    u = __fadd_rn(u, lo);
    u = fmaxf(u, lo);
    return 1.4142135623730951f * erfinv_xla(u);
}

// ---------------- fused mid aggregation + reparameterization (simple loop) ----------------
__global__ void aggz_kernel(const __half* __restrict__ hin,
                            float* __restrict__ o_z, float* __restrict__ o_mu,
                            float* __restrict__ o_lv) {
    int w = (blockIdx.x * blockDim.x + threadIdx.x) >> 5;
    int lane = threadIdx.x & 31;
    if (w >= NN_) return;
    float dd = g_dinv_1[w];
    float4 b4 = *(const float4*)&g_bias2[lane * 4];
    uint2 sraw = *(const uint2*)&hin[(size_t)w * DH + lane * 4];
    float2 s01 = __half22float2(*(__half2*)&sraw.x);
    float2 s23 = __half22float2(*(__half2*)&sraw.y);
    float sn = dd * dd;
    float4 acc;
    acc.x = fmaf(s01.x, sn, b4.x);
    acc.y = fmaf(s01.y, sn, b4.y);
    acc.z = fmaf(s23.x, sn, b4.z);
    acc.w = fmaf(s23.y, sn, b4.w);
    int beg = g_base[w];
    int end = beg + g_cnt[w];
    for (int p = beg; p < end; p++) {
        int2 c = g_ecsr[p];
        float nrm = g_dinv_1[c.x] * dd;
        uint2 vr = *(const uint2*)&hin[(size_t)c.x * DH + lane * 4];
        float2 v01 = __half22float2(*(__half2*)&vr.x);
        float2 v23 = __half22float2(*(__half2*)&vr.y);
        acc.x = fmaf(nrm, v01.x, acc.x);
        acc.y = fmaf(nrm, v01.y, acc.y);
        acc.z = fmaf(nrm, v23.x, acc.z);
        acc.w = fmaf(nrm, v23.y, acc.w);
    }

    float4 lvv;
    lvv.x = __shfl_sync(0xffffffffu, acc.x, lane + 16);
    lvv.y = __shfl_sync(0xffffffffu, acc.y, lane + 16);
    lvv.z = __shfl_sync(0xffffffffu, acc.z, lane + 16);
    lvv.w = __shfl_sync(0xffffffffu, acc.w, lane + 16);

    if (lane < 16) {
        unsigned base = (unsigned)w * 64u + (unsigned)lane * 4u;
        *(float4*)&o_mu[base] = acc;
        float z0 = __fadd_rn(acc.x, __fmul_rn(bits_to_normal(threefry_bits_partitionable(base + 0)), expf(0.5f * lvv.x)));
        float z1 = __fadd_rn(acc.y, __fmul_rn(bits_to_normal(threefry_bits_partitionable(base + 1)), expf(0.5f * lvv.y)));
        float z2 = __fadd_rn(acc.z, __fmul_rn(bits_to_normal(threefry_bits_partitionable(base + 2)), expf(0.5f * lvv.z)));
        float z3 = __fadd_rn(acc.w, __fmul_rn(bits_to_normal(threefry_bits_partitionable(base + 3)), expf(0.5f * lvv.w)));
        *(float4*)&o_z[base] = make_float4(z0, z1, z2, z3);
        uint2 zf;
        *(__half2*)&zf.x = __floats2half2_rn(z0, z1);
        *(__half2*)&zf.y = __floats2half2_rn(z2, z3);
        *(uint2*)&g_zf16[base] = zf;
    } else {
        unsigned base = (unsigned)w * 64u + (unsigned)(lane - 16) * 4u;
        *(float4*)&o_lv[base] = acc;
    }
}

// ---------------- decoder aggregation over fp16 z (64-dim, simple loop) ----------------
__global__ void agg64h_kernel(const __half* __restrict__ zin, float* __restrict__ t) {
    int w = (blockIdx.x * blockDim.x + threadIdx.x) >> 5;
    int lane = threadIdx.x & 31;
    if (w >= NN_) return;
    float dd = g_dinv_1[w];
    float sn = dd * dd;
    uint32_t sraw = *(const uint32_t*)&zin[(size_t)w * DL + lane * 2];
    float2 sv = __half22float2(*(__half2*)&sraw);
    float2 acc = make_float2(sv.x * sn, sv.y * sn);
    int beg = g_base[w];
    int end = beg + g_cnt[w];
    for (int p = beg; p < end; p++) {
        int2 c = g_ecsr[p];
        float nrm = g_dinv_1[c.x] * dd;
        uint32_t vr = *(const uint32_t*)&zin[(size_t)c.x * DL + lane * 2];
        float2 v = __half22float2(*(__half2*)&vr);
        acc.x = fmaf(nrm, v.x, acc.x);
        acc.y = fmaf(nrm, v.y, acc.y);
    }
    *(float2*)&t[(size_t)w * DL + lane * 2] = acc;
}

// ---------------- launch ----------------
extern "C" void kernel_launch(void* const* d_in, const int* in_sizes, int n_in,
                              void* d_out, int out_size) {
    const float* x     = (const float*)d_in[0];
    const float* ew    = (const float*)d_in[1];
    const float* W_enc = (const float*)d_in[2];
    const float* b_enc = (const float*)d_in[3];
    const float* W_mu  = (const float*)d_in[4];
    const float* b_mu  = (const float*)d_in[5];
    const float* W_lv  = (const float*)d_in[6];
    const float* b_lv  = (const float*)d_in[7];
    const float* W_dec = (const float*)d_in[8];
    const float* b_dec = (const float*)d_in[9];
    const void*  eidx  = d_in[10];

    float* out   = (float*)d_out;
    float* o_z   = out;                       // [N,64]
    float* o_rec = out + (size_t)NN_ * DL;    // [N,128]
    float* o_mu  = o_rec + (size_t)NN_ * DH;  // [N,64]
    float* o_lv  = o_mu + (size_t)NN_ * DL;   // [N,64]

    float *p_h, *p_t;
    __half *p_hf16, *p_zf16;
    uint4 *p_bf_enc, *p_bf_mid, *p_bf_dec;
    cudaGetSymbolAddress((void**)&p_h, g_h);
    cudaGetSymbolAddress((void**)&p_t, g_t);
    cudaGetSymbolAddress((void**)&p_hf16, g_hf16);
    cudaGetSymbolAddress((void**)&p_zf16, g_zf16);
    cudaGetSymbolAddress((void**)&p_bf_enc, g_bfrag_enc);
    cudaGetSymbolAddress((void**)&p_bf_mid, g_bfrag_mid);
    cudaGetSymbolAddress((void**)&p_bf_dec, g_bfrag_dec);

    const int NB_SCAN = (NN_ + 1023) / 1024;           // 98
    const int GEMM_GRID = (NN_ + 63) / 64;             // 1563

    // GEMM1 at launch index 3 so the fixed ncu capture slot profiles it.
    detect_kernel<<<1, 128>>>((const unsigned*)eidx);                                   // 0
    bfrag_kernel<<<(8 * 16 * 32 + 255) / 256, 256>>>(W_enc, W_mu, W_lv, W_dec);         // 1
    init_kernel<<<(NN_ + 255) / 256, 256>>>(b_mu, b_lv);                                // 2
    hmma_gemm_kernel<128, true><<<GEMM_GRID, 256>>>(x, NN_, p_bf_enc, p_hf16, nullptr); // 3 (PROFILED)
    deg_kernel<<<(EE_ + 255) / 256, 256>>>(eidx);                                       // 4
    scan1_kernel<<<NB_SCAN, 1024>>>();                                                  // 5
    scan2_kernel<<<1, 128>>>(NB_SCAN);                                                  // 6
    scan3_kernel<<<(NN_ + 255) / 256, 256>>>();                                         // 7
    fill_kernel<<<(EE_ + 255) / 256, 256>>>(eidx, ew);                                  // 8
    sumw_kernel<<<(NN_ + 255) / 256, 256>>>();                                          // 9

    // encoder agg: h = agg_w(hf16) + b_enc
    aggh_kernel<<<(NN_ * 32 + 255) / 256, 256>>>(p_hf16, p_h, b_enc);                   // 10
    // mid GEMM: hf16 = h @ [W_mu|W_lv]
    hmma_gemm_kernel<128, true><<<GEMM_GRID, 256>>>(p_h, NN_, p_bf_mid, p_hf16, nullptr); // 11
    // fused mid agg + reparam
    aggz_kernel<<<(NN_ * 32 + 255) / 256, 256>>>(p_hf16, o_z, o_mu, o_lv);              // 12
    // decoder agg: t = agg(z_fp16)
    agg64h_kernel<<<(NN_ * 32 + 255) / 256, 256>>>(p_zf16, p_t);                        // 13
    // decoder GEMM: recon = t @ W_dec + b_dec
    hmma_gemm_kernel<64, false><<<GEMM_GRID, 256>>>(p_t, NN_, p_bf_dec, o_rec, b_dec);  // 14
}